// round 13
// baseline (speedup 1.0000x reference)
#include <cuda_runtime.h>
#include <cuda_fp16.h>
#include <cstdint>

#define N_NODES 20000
#define N_EDGES 320000
#define F 128
#define FH 64             // F/2 half2 per row
#define R 4
#define NBUCKETS (R * N_NODES)
#define CAP 64            // max edges per (relation,dst) bucket; Poisson(4) => P(>=64) ~ 1e-60
#define NTILES 20         // 5 K-segments x 4 k-chunks of 32

// fused-prep block ranges
#define PREP_I 313        // zero counters + seed minmax
#define PREP_X 5000       // x -> half2
#define PREP_W 320        // W pack
#define PREP_TOTAL (PREP_I + PREP_X + PREP_W)

// fused combine smem layout (uint32 units)
#define BIGA_STRIDE 68    // 64 kpairs + pad 4 (stride 68 mod 32 = 4 -> conflict-free frags)
#define BIGA_SEG   (64 * BIGA_STRIDE)      // 4352
#define WH_OFF     (5 * BIGA_SEG)          // 21760
#define SMEM_UINTS (WH_OFF + 128 * 20)     // + Wh[128][20] = 24320
#define SMEM_BYTES (SMEM_UINTS * 4)        // 97280 B

// ---------------- scratch (device globals; no allocation allowed) ----------------
__device__ uint32_t g_xh[(size_t)N_NODES * FH];       // x in half2 (5 MB)
__device__ uint32_t g_hh[(size_t)N_NODES * FH];       // layer-1 output in half2 (5 MB)
__device__ int      g_cnt[NBUCKETS];
__device__ int2     g_slots[(size_t)NBUCKETS * CAP];
__device__ int      g_mn, g_mx;
__device__ uint32_t g_Wth[2 * 5 * 4 * 128 * 16];      // [layer][seg][kc][n][k-pair] half2

__device__ __forceinline__ uint32_t pack_h2(float a, float b) {
    __half2 h = __floats2half2_rn(a, b);
    return *(uint32_t*)&h;
}
__device__ __forceinline__ float2 unpack_h2(uint32_t u) {
    return __half22float2(*(__half2*)&u);
}

// ---------------- fused prep: counters+seeds | x->fp16 | W pack (one launch) -------------
__global__ void k_prep(const float* __restrict__ x,
                       const float* __restrict__ W1, const float* __restrict__ r1,
                       const float* __restrict__ W2, const float* __restrict__ r2) {
    int blk = blockIdx.x;
    if (blk < PREP_I) {
        int i = blk * 256 + threadIdx.x;
        if (i == 0) { g_mn = 0x7f800000; g_mx = 0; }
        if (i < NBUCKETS) g_cnt[i] = 0;
    } else if (blk < PREP_I + PREP_X) {
        int i = (blk - PREP_I) * 256 + threadIdx.x;   // half2 index
        if (i < N_NODES * FH) {
            float2 v = ((const float2*)x)[i];
            g_xh[i] = pack_h2(v.x, v.y);
        }
    } else {
        int idx = (blk - PREP_I - PREP_X) * 256 + threadIdx.x;  // 2*5*128*64 half2 slots
        if (idx < 2 * 5 * 128 * 64) {
            int layer = idx / 40960;
            int rem   = idx % 40960;
            int seg   = rem / 8192;
            int nj    = rem % 8192;        // n*64 + j
            int n     = nj >> 6;
            int j     = nj & 63;           // k-pair 0..63
            const float* src = (layer == 0) ? ((seg < 4) ? W1 + seg * 16384 : r1)
                                            : ((seg < 4) ? W2 + seg * 16384 : r2);
            uint32_t v = pack_h2(src[(2 * j) * 128 + n], src[(2 * j + 1) * 128 + n]);
            g_Wth[((((size_t)layer * 5 + seg) * 4 + (j >> 4)) * 128 + n) * 16 + (j & 15)] = v;
        }
    }
}

// ---------------- minmax: grid-stride + block reduction -> 2 atomics/block ----------------
__global__ void k_minmax(const float* __restrict__ ew) {
    __shared__ float smn[8], smx[8];
    int tid  = threadIdx.x;
    int lane = tid & 31;
    int wid  = tid >> 5;

    float mn = __int_as_float(0x7f800000), mx = 0.f;
    for (int i = blockIdx.x * blockDim.x + tid; i < N_EDGES; i += gridDim.x * blockDim.x) {
        float v = ew[i];
        mn = fminf(mn, v);
        mx = fmaxf(mx, v);
    }
    #pragma unroll
    for (int o = 16; o; o >>= 1) {
        mn = fminf(mn, __shfl_xor_sync(0xffffffffu, mn, o));
        mx = fmaxf(mx, __shfl_xor_sync(0xffffffffu, mx, o));
    }
    if (lane == 0) { smn[wid] = mn; smx[wid] = mx; }
    __syncthreads();
    if (wid == 0) {
        mn = smn[lane & 7]; mx = smx[lane & 7];
        #pragma unroll
        for (int o = 4; o; o >>= 1) {
            mn = fminf(mn, __shfl_xor_sync(0xffffffffu, mn, o));
            mx = fmaxf(mx, __shfl_xor_sync(0xffffffffu, mx, o));
        }
        if (lane == 0) {
            atomicMin(&g_mn, __float_as_int(mn));
            atomicMax(&g_mx, __float_as_int(mx));
        }
    }
}

// ---------------- bucket build; 2 edges/thread ----------------
__global__ void k_build(const int* __restrict__ src, const int* __restrict__ dst,
                        const int* __restrict__ et, const float* __restrict__ ew) {
    int base = (blockIdx.x * blockDim.x + threadIdx.x) * 2;
    float mn = __int_as_float(g_mn);
    float mx = __int_as_float(g_mx);
    float inv = 1.0f / (mx - mn + 1e-8f);
    #pragma unroll
    for (int j = 0; j < 2; j++) {
        int e = base + j;
        if (e >= N_EDGES) break;
        float w = (ew[e] - mn) * inv;
        int b = et[e] * N_NODES + dst[e];
        int slot = atomicAdd(&g_cnt[b], 1);
        if (slot < CAP)
            g_slots[(size_t)b * CAP + slot] = make_int2(src[e], __float_as_int(w));
    }
}

#define MMA_F16(d, a0, a1, a2, a3, b0, b1)                                    \
    asm volatile("mma.sync.aligned.m16n8k16.row.col.f32.f16.f16.f32 "         \
                 "{%0,%1,%2,%3}, {%4,%5,%6,%7}, {%8,%9}, {%0,%1,%2,%3};"      \
                 : "+f"((d)[0]), "+f"((d)[1]), "+f"((d)[2]), "+f"((d)[3])     \
                 : "r"(a0), "r"(a1), "r"(a2), "r"(a3), "r"(b0), "r"(b1))

// ---------------- fused combine: aggregate CTA's own A-rows into smem, then GEMM ----------
// Per CTA (64 rows): prologue aggregates buckets (r, row0+d) for r<4, d<64 into smem panel
// bigA[5][64][68] (seg 4 = Xin copy), then fp16 GEMM over 20 W tiles streams only W.
// No global A traffic, no separate agg kernel. Arithmetic identical to split version.
__global__ void __launch_bounds__(256, 2)
k_fused(const float* __restrict__ bias, float* __restrict__ out, int layer) {
    extern __shared__ uint32_t sm[];
    uint32_t* bigA = sm;                 // [5][64][BIGA_STRIDE]
    uint32_t* WhS  = sm + WH_OFF;        // [128][20]

    const uint32_t* Xin = (layer == 0) ? g_xh : g_hh;

    int t    = threadIdx.x;
    int lane = t & 31;
    int w    = t >> 5;          // warp 0..7
    int row0 = blockIdx.x * 64;

    // ---- phase 1: aggregate this CTA's A-panel (tasks: 256 buckets + 64 Xin copies) ----
    for (int task = w; task < 320; task += 8) {
        if (task < 256) {
            int seg  = task >> 6;
            int drow = task & 63;
            int d    = row0 + drow;
            float a0 = 0.f, a1 = 0.f, a2 = 0.f, a3 = 0.f;
            if (d < N_NODES) {
                int b = seg * N_NODES + d;
                int n = g_cnt[b];
                n = n > CAP ? CAP : n;
                const int2* sl = g_slots + (size_t)b * CAP;
                for (int i = 0; i < n; i += 4) {
                    int4 ea = __ldg((const int4*)&sl[i]);
                    int4 eb = __ldg((const int4*)&sl[i + 2]);
                    float w0 = (i + 0 < n) ? __int_as_float(ea.y) : 0.f;
                    float w1 = (i + 1 < n) ? __int_as_float(ea.w) : 0.f;
                    float w2 = (i + 2 < n) ? __int_as_float(eb.y) : 0.f;
                    float w3 = (i + 3 < n) ? __int_as_float(eb.w) : 0.f;
                    unsigned s0 = min((unsigned)ea.x, (unsigned)(N_NODES - 1));
                    unsigned s1 = min((unsigned)ea.z, (unsigned)(N_NODES - 1));
                    unsigned s2 = min((unsigned)eb.x, (unsigned)(N_NODES - 1));
                    unsigned s3 = min((unsigned)eb.z, (unsigned)(N_NODES - 1));
                    uint2 p0 = *(const uint2*)(Xin + (size_t)s0 * FH + lane * 2);
                    uint2 p1 = *(const uint2*)(Xin + (size_t)s1 * FH + lane * 2);
                    uint2 p2 = *(const uint2*)(Xin + (size_t)s2 * FH + lane * 2);
                    uint2 p3 = *(const uint2*)(Xin + (size_t)s3 * FH + lane * 2);
                    float2 v;
                    v = unpack_h2(p0.x); a0 += w0 * v.x; a1 += w0 * v.y;
                    v = unpack_h2(p0.y); a2 += w0 * v.x; a3 += w0 * v.y;
                    v = unpack_h2(p1.x); a0 += w1 * v.x; a1 += w1 * v.y;
                    v = unpack_h2(p1.y); a2 += w1 * v.x; a3 += w1 * v.y;
                    v = unpack_h2(p2.x); a0 += w2 * v.x; a1 += w2 * v.y;
                    v = unpack_h2(p2.y); a2 += w2 * v.x; a3 += w2 * v.y;
                    v = unpack_h2(p3.x); a0 += w3 * v.x; a1 += w3 * v.y;
                    v = unpack_h2(p3.y); a2 += w3 * v.x; a3 += w3 * v.y;
                }
            }
            uint32_t* dst = bigA + seg * BIGA_SEG + drow * BIGA_STRIDE + lane * 2;
            dst[0] = pack_h2(a0, a1);
            dst[1] = pack_h2(a2, a3);
        } else {
            int drow = task - 256;
            int grow = row0 + drow;
            uint2 p = (grow < N_NODES)
                    ? *(const uint2*)(Xin + (size_t)grow * FH + lane * 2)
                    : make_uint2(0u, 0u);
            uint32_t* dst = bigA + 4 * BIGA_SEG + drow * BIGA_STRIDE + lane * 2;
            dst[0] = p.x;
            dst[1] = p.y;
        }
    }

    // ---- phase 2: GEMM (A from smem panel; W tiles streamed with reg prefetch) ----
    int wm   = w & 1;           // row group: rows wm*32..+31
    int wn   = w >> 1;          // col group: cols wn*32..+31
    int gid  = lane >> 2;       // 0..7
    int tid4 = lane & 3;        // 0..3

    float acc[2][4][4];
    #pragma unroll
    for (int mt = 0; mt < 2; mt++)
        #pragma unroll
        for (int nt = 0; nt < 4; nt++)
            #pragma unroll
            for (int q = 0; q < 4; q++) acc[mt][nt][q] = 0.f;

    int wn_[2], wq[2];          // B: 128 cols x 4 uint4 slots; 2/thread
    #pragma unroll
    for (int it = 0; it < 2; it++) {
        int idx = t + it * 256;
        wn_[it] = idx >> 2;
        wq[it]  = idx & 3;
    }

    uint4 pw[2];
    #define LOAD_W(tile)                                                            \
    do {                                                                            \
        int seg_ = (tile) >> 2;                                                     \
        int kc_  = (tile) & 3;                                                      \
        const uint32_t* wt_ = g_Wth + (((size_t)layer * 5 + seg_) * 4 + kc_) * 2048;\
        _Pragma("unroll")                                                           \
        for (int it = 0; it < 2; it++)                                              \
            pw[it] = *(const uint4*)(wt_ + wn_[it] * 16 + wq[it] * 4);              \
    } while (0)

    LOAD_W(0);

    for (int tile = 0; tile < NTILES; tile++) {
        __syncthreads();   // tile 0: doubles as agg-phase barrier; else Wh reuse gate
        #pragma unroll
        for (int it = 0; it < 2; it++)
            *(uint4*)&WhS[wn_[it] * 20 + wq[it] * 4] = pw[it];
        __syncthreads();

        if (tile + 1 < NTILES) LOAD_W(tile + 1);

        int seg = tile >> 2;
        int kc  = tile & 3;
        const uint32_t* Ap = bigA + seg * BIGA_SEG + kc * 16;

        #pragma unroll
        for (int kk = 0; kk < 16; kk += 8) {
            uint32_t a[2][4];
            #pragma unroll
            for (int mt = 0; mt < 2; mt++) {
                int row = wm * 32 + mt * 16 + gid;
                const uint32_t* r0p = Ap + row * BIGA_STRIDE;
                const uint32_t* r8p = Ap + (row + 8) * BIGA_STRIDE;
                a[mt][0] = r0p[kk + tid4];
                a[mt][1] = r8p[kk + tid4];
                a[mt][2] = r0p[kk + tid4 + 4];
                a[mt][3] = r8p[kk + tid4 + 4];
            }
            #pragma unroll
            for (int nt = 0; nt < 4; nt++) {
                int col = wn * 32 + nt * 8 + gid;
                uint32_t b0 = WhS[col * 20 + kk + tid4];
                uint32_t b1 = WhS[col * 20 + kk + tid4 + 4];
                MMA_F16(acc[0][nt], a[0][0], a[0][1], a[0][2], a[0][3], b0, b1);
                MMA_F16(acc[1][nt], a[1][0], a[1][1], a[1][2], a[1][3], b0, b1);
            }
        }
    }
    #undef LOAD_W

    // ---- epilogue ----
    #pragma unroll
    for (int mt = 0; mt < 2; mt++) {
        int rbase = row0 + wm * 32 + mt * 16 + gid;
        #pragma unroll
        for (int half = 0; half < 2; half++) {
            int grow = rbase + half * 8;
            if (grow >= N_NODES) continue;
            #pragma unroll
            for (int nt = 0; nt < 4; nt++) {
                int col = wn * 32 + nt * 8 + tid4 * 2;
                float v0 = acc[mt][nt][half * 2 + 0] + __ldg(&bias[col]);
                float v1 = acc[mt][nt][half * 2 + 1] + __ldg(&bias[col + 1]);
                if (layer == 0) {
                    v0 = fmaxf(v0, 0.f); v1 = fmaxf(v1, 0.f);
                    g_hh[(size_t)grow * FH + (col >> 1)] = pack_h2(v0, v1);
                } else {
                    *(float2*)(out + (size_t)grow * F + col) = make_float2(v0, v1);
                }
            }
        }
    }
}

// ---------------- launcher ----------------
extern "C" void kernel_launch(void* const* d_in, const int* in_sizes, int n_in,
                              void* d_out, int out_size) {
    const float* x     = (const float*)d_in[0];
    const int*   ei    = (const int*)d_in[1];     // [2, E]
    const int*   srcp  = ei;
    const int*   dstp  = ei + N_EDGES;
    const int*   et    = (const int*)d_in[2];
    const float* ew    = (const float*)d_in[3];
    const float* W1    = (const float*)d_in[4];
    const float* root1 = (const float*)d_in[5];
    const float* b1    = (const float*)d_in[6];
    const float* W2    = (const float*)d_in[7];
    const float* root2 = (const float*)d_in[8];
    const float* b2    = (const float*)d_in[9];
    float* out = (float*)d_out;

    cudaFuncSetAttribute(k_fused, cudaFuncAttributeMaxDynamicSharedMemorySize, SMEM_BYTES);

    const int bblocks = (N_EDGES / 2 + 255) / 256;
    const int cblocks = (N_NODES + 63) / 64;                  // 313

    // prep: fused init/x->fp16/W-pack, minmax (block-reduced), bucket build
    k_prep<<<PREP_TOTAL, 256>>>(x, W1, root1, W2, root2);
    k_minmax<<<296, 256>>>(ew);
    k_build<<<bblocks, 256>>>(srcp, dstp, et, ew);

    // layer 1: per-CTA aggregate + GEMM; g_hh = relu([A|xh] @ [W1;root1] + b1)
    k_fused<<<cblocks, 256, SMEM_BYTES>>>(b1, out, /*layer=*/0);

    // layer 2: per-CTA aggregate + GEMM; out = [A|hh] @ [W2;root2] + b2
    k_fused<<<cblocks, 256, SMEM_BYTES>>>(b2, out, /*layer=*/1);
}

// round 14
// speedup vs baseline: 1.5543x; 1.5543x over previous
#include <cuda_runtime.h>
#include <cuda_fp16.h>
#include <cstdint>

#define N_NODES 20000
#define N_EDGES 320000
#define F 128
#define FH 64             // F/2 half2 per row
#define R 4
#define NBUCKETS (R * N_NODES)
#define CAP 64            // max edges per (relation,dst) bucket; Poisson(4) => P(>=64) ~ 1e-60
#define NTILES 20         // 5 K-segments x 4 k-chunks of 32

// fused-prep block ranges
#define PREP_I 313        // zero counters + seed minmax
#define PREP_X 5000       // x -> half2
#define PREP_W 320        // W pack
#define PREP_TOTAL (PREP_I + PREP_X + PREP_W)

// ---------------- scratch (device globals; no allocation allowed) ----------------
__device__ uint32_t g_Ah[(size_t)R * N_NODES * FH];   // per-relation messages, half2 (20.5 MB)
__device__ uint32_t g_xh[(size_t)N_NODES * FH];       // x in half2 (5 MB)
__device__ uint32_t g_hh[(size_t)N_NODES * FH];       // layer-1 output in half2 (5 MB)
__device__ int      g_cnt[NBUCKETS];
__device__ int2     g_slots[(size_t)NBUCKETS * CAP];
__device__ int      g_mn, g_mx;
__device__ uint32_t g_Wth[2 * 5 * 4 * 128 * 16];      // [layer][seg][kc][n][k-pair] half2

__device__ __forceinline__ uint32_t pack_h2(float a, float b) {
    __half2 h = __floats2half2_rn(a, b);
    return *(uint32_t*)&h;
}
__device__ __forceinline__ float2 unpack_h2(uint32_t u) {
    return __half22float2(*(__half2*)&u);
}

// ---------------- fused prep: counters+seeds | x->fp16 | W pack (one launch) -------------
__global__ void k_prep(const float* __restrict__ x,
                       const float* __restrict__ W1, const float* __restrict__ r1,
                       const float* __restrict__ W2, const float* __restrict__ r2) {
    int blk = blockIdx.x;
    if (blk < PREP_I) {
        int i = blk * 256 + threadIdx.x;
        if (i == 0) { g_mn = 0x7f800000; g_mx = 0; }
        if (i < NBUCKETS) g_cnt[i] = 0;
    } else if (blk < PREP_I + PREP_X) {
        int i = (blk - PREP_I) * 256 + threadIdx.x;   // half2 index
        if (i < N_NODES * FH) {
            float2 v = ((const float2*)x)[i];
            g_xh[i] = pack_h2(v.x, v.y);
        }
    } else {
        int idx = (blk - PREP_I - PREP_X) * 256 + threadIdx.x;  // 2*5*128*64 half2 slots
        if (idx < 2 * 5 * 128 * 64) {
            int layer = idx / 40960;
            int rem   = idx % 40960;
            int seg   = rem / 8192;
            int nj    = rem % 8192;        // n*64 + j
            int n     = nj >> 6;
            int j     = nj & 63;           // k-pair 0..63
            const float* src = (layer == 0) ? ((seg < 4) ? W1 + seg * 16384 : r1)
                                            : ((seg < 4) ? W2 + seg * 16384 : r2);
            uint32_t v = pack_h2(src[(2 * j) * 128 + n], src[(2 * j + 1) * 128 + n]);
            g_Wth[((((size_t)layer * 5 + seg) * 4 + (j >> 4)) * 128 + n) * 16 + (j & 15)] = v;
        }
    }
}

// ---------------- minmax: grid-stride + block reduction -> 2 atomics/block ----------------
__global__ void k_minmax(const float* __restrict__ ew) {
    __shared__ float smn[8], smx[8];
    int tid  = threadIdx.x;
    int lane = tid & 31;
    int wid  = tid >> 5;

    float mn = __int_as_float(0x7f800000), mx = 0.f;
    for (int i = blockIdx.x * blockDim.x + tid; i < N_EDGES; i += gridDim.x * blockDim.x) {
        float v = ew[i];
        mn = fminf(mn, v);
        mx = fmaxf(mx, v);
    }
    #pragma unroll
    for (int o = 16; o; o >>= 1) {
        mn = fminf(mn, __shfl_xor_sync(0xffffffffu, mn, o));
        mx = fmaxf(mx, __shfl_xor_sync(0xffffffffu, mx, o));
    }
    if (lane == 0) { smn[wid] = mn; smx[wid] = mx; }
    __syncthreads();
    if (wid == 0) {
        mn = smn[lane & 7]; mx = smx[lane & 7];
        #pragma unroll
        for (int o = 4; o; o >>= 1) {
            mn = fminf(mn, __shfl_xor_sync(0xffffffffu, mn, o));
            mx = fmaxf(mx, __shfl_xor_sync(0xffffffffu, mx, o));
        }
        if (lane == 0) {
            atomicMin(&g_mn, __float_as_int(mn));
            atomicMax(&g_mx, __float_as_int(mx));
        }
    }
}

// ---------------- bucket build; 2 edges/thread ----------------
__global__ void k_build(const int* __restrict__ src, const int* __restrict__ dst,
                        const int* __restrict__ et, const float* __restrict__ ew) {
    int base = (blockIdx.x * blockDim.x + threadIdx.x) * 2;
    float mn = __int_as_float(g_mn);
    float mx = __int_as_float(g_mx);
    float inv = 1.0f / (mx - mn + 1e-8f);
    #pragma unroll
    for (int j = 0; j < 2; j++) {
        int e = base + j;
        if (e >= N_EDGES) break;
        float w = (ew[e] - mn) * inv;
        int b = et[e] * N_NODES + dst[e];
        int slot = atomicAdd(&g_cnt[b], 1);
        if (slot < CAP)
            g_slots[(size_t)b * CAP + slot] = make_int2(src[e], __float_as_int(w));
    }
}

// ---------------- aggregate: Ah[b] = sum over bucket of w * xin[src] ----------------------
// 2 buckets per warp, 16 lanes each; lane owns 16B (uint4 = 4 half2 = 8 floats).
// LDG.128 gathers, STG.128 store, 2 independent chains/warp. Per-element summation order
// identical to previous version (bit-identical results).
__global__ void k_agg(int use_h) {
    int warp_g = (int)(((size_t)blockIdx.x * blockDim.x + threadIdx.x) >> 5);
    int lane   = threadIdx.x & 31;
    int b      = warp_g * 2 + (lane >> 4);
    if (b >= NBUCKETS) return;
    int l = lane & 15;                     // owns half2 indices l*4 .. l*4+3
    const uint32_t* xin = use_h ? g_hh : g_xh;

    int n = g_cnt[b];
    n = n > CAP ? CAP : n;
    const int2* sl = g_slots + (size_t)b * CAP;

    float a0 = 0.f, a1 = 0.f, a2 = 0.f, a3 = 0.f;
    float a4 = 0.f, a5 = 0.f, a6 = 0.f, a7 = 0.f;
    for (int i = 0; i < n; i += 4) {
        int4 ea = __ldg((const int4*)&sl[i]);
        int4 eb = __ldg((const int4*)&sl[i + 2]);
        float w0 = (i + 0 < n) ? __int_as_float(ea.y) : 0.f;
        float w1 = (i + 1 < n) ? __int_as_float(ea.w) : 0.f;
        float w2 = (i + 2 < n) ? __int_as_float(eb.y) : 0.f;
        float w3 = (i + 3 < n) ? __int_as_float(eb.w) : 0.f;
        uint32_t o0 = min((unsigned)ea.x, (unsigned)(N_NODES - 1)) * FH + l * 4;
        uint32_t o1 = min((unsigned)ea.z, (unsigned)(N_NODES - 1)) * FH + l * 4;
        uint32_t o2 = min((unsigned)eb.x, (unsigned)(N_NODES - 1)) * FH + l * 4;
        uint32_t o3 = min((unsigned)eb.z, (unsigned)(N_NODES - 1)) * FH + l * 4;
        // 4 independent 256B row gathers (uint4 per lane)
        uint4 p0 = *(const uint4*)(xin + o0);
        uint4 p1 = *(const uint4*)(xin + o1);
        uint4 p2 = *(const uint4*)(xin + o2);
        uint4 p3 = *(const uint4*)(xin + o3);
        float2 v;
        v = unpack_h2(p0.x); a0 += w0 * v.x; a1 += w0 * v.y;
        v = unpack_h2(p0.y); a2 += w0 * v.x; a3 += w0 * v.y;
        v = unpack_h2(p0.z); a4 += w0 * v.x; a5 += w0 * v.y;
        v = unpack_h2(p0.w); a6 += w0 * v.x; a7 += w0 * v.y;
        v = unpack_h2(p1.x); a0 += w1 * v.x; a1 += w1 * v.y;
        v = unpack_h2(p1.y); a2 += w1 * v.x; a3 += w1 * v.y;
        v = unpack_h2(p1.z); a4 += w1 * v.x; a5 += w1 * v.y;
        v = unpack_h2(p1.w); a6 += w1 * v.x; a7 += w1 * v.y;
        v = unpack_h2(p2.x); a0 += w2 * v.x; a1 += w2 * v.y;
        v = unpack_h2(p2.y); a2 += w2 * v.x; a3 += w2 * v.y;
        v = unpack_h2(p2.z); a4 += w2 * v.x; a5 += w2 * v.y;
        v = unpack_h2(p2.w); a6 += w2 * v.x; a7 += w2 * v.y;
        v = unpack_h2(p3.x); a0 += w3 * v.x; a1 += w3 * v.y;
        v = unpack_h2(p3.y); a2 += w3 * v.x; a3 += w3 * v.y;
        v = unpack_h2(p3.z); a4 += w3 * v.x; a5 += w3 * v.y;
        v = unpack_h2(p3.w); a6 += w3 * v.x; a7 += w3 * v.y;
    }
    uint4 o = make_uint4(pack_h2(a0, a1), pack_h2(a2, a3),
                         pack_h2(a4, a5), pack_h2(a6, a7));
    *(uint4*)(g_Ah + (size_t)b * FH + l * 4) = o;
}

#define MMA_F16(d, a0, a1, a2, a3, b0, b1)                                    \
    asm volatile("mma.sync.aligned.m16n8k16.row.col.f32.f16.f16.f32 "         \
                 "{%0,%1,%2,%3}, {%4,%5,%6,%7}, {%8,%9}, {%0,%1,%2,%3};"      \
                 : "+f"((d)[0]), "+f"((d)[1]), "+f"((d)[2]), "+f"((d)[3])     \
                 : "r"(a0), "r"(a1), "r"(a2), "r"(a3), "r"(b0), "r"(b1))

// ---------------- combine: out = relu?( [A0|A1|A2|A3|Xin] @ [W;root] + b ) ----------------
// fp16 tensor-core GEMM (m16n8k16, fp32 acc). All inputs pre-packed half2: STS is pure copy.
// BM=64, BN=128, BK=32, 256 threads = 8 warps (2x4), warp tile 32x32.
__global__ void __launch_bounds__(256, 2)
k_combine(const float* __restrict__ bias, float* __restrict__ out, int layer) {
    __shared__ uint32_t Xs[64][20];    // half2 A tile: 16 k-pairs + pad 4
    __shared__ uint32_t Wh[128][20];   // half2 B tile [col][k-pair]: 16 + pad 4

    const uint32_t* Xin = (layer == 0) ? g_xh : g_hh;

    int t    = threadIdx.x;
    int lane = t & 31;
    int w    = t >> 5;          // warp 0..7
    int wm   = w & 1;           // row group: rows wm*32..+31
    int wn   = w >> 1;          // col group: cols wn*32..+31
    int gid  = lane >> 2;       // 0..7
    int tid4 = lane & 3;        // 0..3
    int row0 = blockIdx.x * 64;

    float acc[2][4][4];
    #pragma unroll
    for (int mt = 0; mt < 2; mt++)
        #pragma unroll
        for (int nt = 0; nt < 4; nt++)
            #pragma unroll
            for (int q = 0; q < 4; q++) acc[mt][nt][q] = 0.f;

    int arow = t >> 2;          // A: 64 rows x 4 uint4 slots; 1/thread
    int aq   = t & 3;
    int wn_[2], wq[2];          // B: 128 cols x 4 uint4 slots; 2/thread
    #pragma unroll
    for (int it = 0; it < 2; it++) {
        int idx = t + it * 256;
        wn_[it] = idx >> 2;
        wq[it]  = idx & 3;
    }

    uint4 pa, pw[2];
    #define LOAD_TILE(tile)                                                         \
    do {                                                                            \
        int seg_ = (tile) >> 2;                                                     \
        int kc_  = (tile) & 3;                                                      \
        const uint32_t* srcA_ = (seg_ < 4) ? (g_Ah + (size_t)seg_ * N_NODES * FH) : Xin; \
        const uint32_t* wt_ = g_Wth + (((size_t)layer * 5 + seg_) * 4 + kc_) * 2048;\
        int grow_ = row0 + arow;                                                    \
        pa = (grow_ < N_NODES)                                                      \
           ? *(const uint4*)(srcA_ + (size_t)grow_ * FH + kc_ * 16 + aq * 4)        \
           : make_uint4(0u, 0u, 0u, 0u);                                            \
        _Pragma("unroll")                                                           \
        for (int it = 0; it < 2; it++)                                              \
            pw[it] = *(const uint4*)(wt_ + wn_[it] * 16 + wq[it] * 4);              \
    } while (0)

    LOAD_TILE(0);

    for (int tile = 0; tile < NTILES; tile++) {
        __syncthreads();
        *(uint4*)&Xs[arow][aq * 4] = pa;
        #pragma unroll
        for (int it = 0; it < 2; it++)
            *(uint4*)&Wh[wn_[it]][wq[it] * 4] = pw[it];
        __syncthreads();

        if (tile + 1 < NTILES) LOAD_TILE(tile + 1);

        #pragma unroll
        for (int kk = 0; kk < 16; kk += 8) {
            uint32_t a[2][4];
            #pragma unroll
            for (int mt = 0; mt < 2; mt++) {
                int row = wm * 32 + mt * 16 + gid;
                a[mt][0] = Xs[row][kk + tid4];
                a[mt][1] = Xs[row + 8][kk + tid4];
                a[mt][2] = Xs[row][kk + tid4 + 4];
                a[mt][3] = Xs[row + 8][kk + tid4 + 4];
            }
            #pragma unroll
            for (int nt = 0; nt < 4; nt++) {
                int col = wn * 32 + nt * 8 + gid;
                uint32_t b0 = Wh[col][kk + tid4];
                uint32_t b1 = Wh[col][kk + tid4 + 4];
                MMA_F16(acc[0][nt], a[0][0], a[0][1], a[0][2], a[0][3], b0, b1);
                MMA_F16(acc[1][nt], a[1][0], a[1][1], a[1][2], a[1][3], b0, b1);
            }
        }
    }
    #undef LOAD_TILE

    #pragma unroll
    for (int mt = 0; mt < 2; mt++) {
        int rbase = row0 + wm * 32 + mt * 16 + gid;
        #pragma unroll
        for (int half = 0; half < 2; half++) {
            int grow = rbase + half * 8;
            if (grow >= N_NODES) continue;
            #pragma unroll
            for (int nt = 0; nt < 4; nt++) {
                int col = wn * 32 + nt * 8 + tid4 * 2;
                float v0 = acc[mt][nt][half * 2 + 0] + __ldg(&bias[col]);
                float v1 = acc[mt][nt][half * 2 + 1] + __ldg(&bias[col + 1]);
                if (layer == 0) {
                    v0 = fmaxf(v0, 0.f); v1 = fmaxf(v1, 0.f);
                    g_hh[(size_t)grow * FH + (col >> 1)] = pack_h2(v0, v1);
                } else {
                    *(float2*)(out + (size_t)grow * F + col) = make_float2(v0, v1);
                }
            }
        }
    }
}

// ---------------- launcher ----------------
extern "C" void kernel_launch(void* const* d_in, const int* in_sizes, int n_in,
                              void* d_out, int out_size) {
    const float* x     = (const float*)d_in[0];
    const int*   ei    = (const int*)d_in[1];     // [2, E]
    const int*   srcp  = ei;
    const int*   dstp  = ei + N_EDGES;
    const int*   et    = (const int*)d_in[2];
    const float* ew    = (const float*)d_in[3];
    const float* W1    = (const float*)d_in[4];
    const float* root1 = (const float*)d_in[5];
    const float* b1    = (const float*)d_in[6];
    const float* W2    = (const float*)d_in[7];
    const float* root2 = (const float*)d_in[8];
    const float* b2    = (const float*)d_in[9];
    float* out = (float*)d_out;

    const int bblocks = (N_EDGES / 2 + 255) / 256;
    const int cblocks = (N_NODES + 63) / 64;                  // 313
    const int ablocks = (NBUCKETS / 2 * 32 + 255) / 256;      // 2 buckets per warp -> 5000

    // prep: fused init/x->fp16/W-pack, minmax (block-reduced), bucket build
    k_prep<<<PREP_TOTAL, 256>>>(x, W1, root1, W2, root2);
    k_minmax<<<296, 256>>>(ew);
    k_build<<<bblocks, 256>>>(srcp, dstp, et, ew);

    // layer 1: Ah = gather(g_xh); g_hh = relu([Ah|xh] @ [W1;root1] + b1)
    k_agg<<<ablocks, 256>>>(/*use_h=*/0);
    k_combine<<<cblocks, 256>>>(b1, out, /*layer=*/0);

    // layer 2: Ah = gather(g_hh); out = [Ah|hh] @ [W2;root2] + b2
    k_agg<<<ablocks, 256>>>(/*use_h=*/1);
    k_combine<<<cblocks, 256>>>(b2, out, /*layer=*/1);
}

// round 15
// speedup vs baseline: 1.6109x; 1.0364x over previous
#include <cuda_runtime.h>
#include <cuda_fp16.h>
#include <cstdint>

#define N_NODES 20000
#define N_EDGES 320000
#define F 128
#define FH 64             // F/2 half2 per row
#define R 4
#define NBUCKETS (R * N_NODES)
#define CAP 64            // max edges per (relation,dst) bucket; Poisson(4) => P(>=64) ~ 1e-60
#define NTILES 20         // 5 K-segments x 4 k-chunks of 32

// prep_a block ranges (init | x->fp16)
#define PREP_I 313        // zero counters + seed minmax
#define PREP_X 5000       // x -> half2
#define PREPA_TOTAL (PREP_I + PREP_X)
#define PREPB_TOTAL 320   // W pack

// ---------------- scratch (device globals; no allocation allowed) ----------------
__device__ uint32_t g_Ah[(size_t)R * N_NODES * FH];   // per-relation messages, half2 (20.5 MB)
__device__ uint32_t g_xh[(size_t)N_NODES * FH];       // x in half2 (5 MB)
__device__ uint32_t g_hh[(size_t)N_NODES * FH];       // layer-1 output in half2 (5 MB)
__device__ int      g_cnt[NBUCKETS];
__device__ int2     g_slots[(size_t)NBUCKETS * CAP];
__device__ int      g_mn, g_mx;
__device__ uint32_t g_Wth[2 * 5 * 4 * 128 * 16];      // [layer][seg][kc][n][k-pair] half2

__device__ __forceinline__ uint32_t pack_h2(float a, float b) {
    __half2 h = __floats2half2_rn(a, b);
    return *(uint32_t*)&h;
}
__device__ __forceinline__ float2 unpack_h2(uint32_t u) {
    return __half22float2(*(__half2*)&u);
}

// ---------------- prep A: counters+seeds | x->fp16 ----------------
__global__ void k_prep_a(const float* __restrict__ x) {
    int blk = blockIdx.x;
    if (blk < PREP_I) {
        int i = blk * 256 + threadIdx.x;
        if (i == 0) { g_mn = 0x7f800000; g_mx = 0; }
        if (i < NBUCKETS) g_cnt[i] = 0;
    } else {
        int i = (blk - PREP_I) * 256 + threadIdx.x;   // half2 index
        if (i < N_NODES * FH) {
            float2 v = ((const float2*)x)[i];
            g_xh[i] = pack_h2(v.x, v.y);
        }
    }
}

// ---------------- prep B: W transpose + fp16 pack ----------------
__global__ void k_prep_b(const float* __restrict__ W1, const float* __restrict__ r1,
                         const float* __restrict__ W2, const float* __restrict__ r2) {
    int idx = blockIdx.x * 256 + threadIdx.x;         // 2*5*128*64 half2 slots
    if (idx >= 2 * 5 * 128 * 64) return;
    int layer = idx / 40960;
    int rem   = idx % 40960;
    int seg   = rem / 8192;
    int nj    = rem % 8192;        // n*64 + j
    int n     = nj >> 6;
    int j     = nj & 63;           // k-pair 0..63
    const float* src = (layer == 0) ? ((seg < 4) ? W1 + seg * 16384 : r1)
                                    : ((seg < 4) ? W2 + seg * 16384 : r2);
    uint32_t v = pack_h2(src[(2 * j) * 128 + n], src[(2 * j + 1) * 128 + n]);
    g_Wth[((((size_t)layer * 5 + seg) * 4 + (j >> 4)) * 128 + n) * 16 + (j & 15)] = v;
}

// ---------------- minmax: grid-stride + block reduction -> 2 atomics/block ----------------
__global__ void k_minmax(const float* __restrict__ ew) {
    __shared__ float smn[8], smx[8];
    int tid  = threadIdx.x;
    int lane = tid & 31;
    int wid  = tid >> 5;

    float mn = __int_as_float(0x7f800000), mx = 0.f;
    for (int i = blockIdx.x * blockDim.x + tid; i < N_EDGES; i += gridDim.x * blockDim.x) {
        float v = ew[i];
        mn = fminf(mn, v);
        mx = fmaxf(mx, v);
    }
    #pragma unroll
    for (int o = 16; o; o >>= 1) {
        mn = fminf(mn, __shfl_xor_sync(0xffffffffu, mn, o));
        mx = fmaxf(mx, __shfl_xor_sync(0xffffffffu, mx, o));
    }
    if (lane == 0) { smn[wid] = mn; smx[wid] = mx; }
    __syncthreads();
    if (wid == 0) {
        mn = smn[lane & 7]; mx = smx[lane & 7];
        #pragma unroll
        for (int o = 4; o; o >>= 1) {
            mn = fminf(mn, __shfl_xor_sync(0xffffffffu, mn, o));
            mx = fmaxf(mx, __shfl_xor_sync(0xffffffffu, mx, o));
        }
        if (lane == 0) {
            atomicMin(&g_mn, __float_as_int(mn));
            atomicMax(&g_mx, __float_as_int(mx));
        }
    }
}

// ---------------- bucket build; 2 edges/thread ----------------
__global__ void k_build(const int* __restrict__ src, const int* __restrict__ dst,
                        const int* __restrict__ et, const float* __restrict__ ew) {
    int base = (blockIdx.x * blockDim.x + threadIdx.x) * 2;
    float mn = __int_as_float(g_mn);
    float mx = __int_as_float(g_mx);
    float inv = 1.0f / (mx - mn + 1e-8f);
    #pragma unroll
    for (int j = 0; j < 2; j++) {
        int e = base + j;
        if (e >= N_EDGES) break;
        float w = (ew[e] - mn) * inv;
        int b = et[e] * N_NODES + dst[e];
        int slot = atomicAdd(&g_cnt[b], 1);
        if (slot < CAP)
            g_slots[(size_t)b * CAP + slot] = make_int2(src[e], __float_as_int(w));
    }
}

// ---------------- aggregate (R12 version: 1 bucket/warp, uint2 lanes; best measured) ------
__global__ void k_agg(int use_h) {
    int b = (int)(((size_t)blockIdx.x * blockDim.x + threadIdx.x) >> 5);
    if (b >= NBUCKETS) return;
    int lane = threadIdx.x & 31;
    const uint32_t* xin = use_h ? g_hh : g_xh;

    int n = g_cnt[b];
    n = n > CAP ? CAP : n;
    const int2* sl = g_slots + (size_t)b * CAP;

    float a0 = 0.f, a1 = 0.f, a2 = 0.f, a3 = 0.f;
    for (int i = 0; i < n; i += 4) {
        int4 ea = __ldg((const int4*)&sl[i]);
        int4 eb = __ldg((const int4*)&sl[i + 2]);
        float w0 = (i + 0 < n) ? __int_as_float(ea.y) : 0.f;
        float w1 = (i + 1 < n) ? __int_as_float(ea.w) : 0.f;
        float w2 = (i + 2 < n) ? __int_as_float(eb.y) : 0.f;
        float w3 = (i + 3 < n) ? __int_as_float(eb.w) : 0.f;
        unsigned s0 = min((unsigned)ea.x, (unsigned)(N_NODES - 1));
        unsigned s1 = min((unsigned)ea.z, (unsigned)(N_NODES - 1));
        unsigned s2 = min((unsigned)eb.x, (unsigned)(N_NODES - 1));
        unsigned s3 = min((unsigned)eb.z, (unsigned)(N_NODES - 1));
        uint2 p0 = *(const uint2*)(xin + (size_t)s0 * FH + lane * 2);
        uint2 p1 = *(const uint2*)(xin + (size_t)s1 * FH + lane * 2);
        uint2 p2 = *(const uint2*)(xin + (size_t)s2 * FH + lane * 2);
        uint2 p3 = *(const uint2*)(xin + (size_t)s3 * FH + lane * 2);
        float2 v;
        v = unpack_h2(p0.x); a0 += w0 * v.x; a1 += w0 * v.y;
        v = unpack_h2(p0.y); a2 += w0 * v.x; a3 += w0 * v.y;
        v = unpack_h2(p1.x); a0 += w1 * v.x; a1 += w1 * v.y;
        v = unpack_h2(p1.y); a2 += w1 * v.x; a3 += w1 * v.y;
        v = unpack_h2(p2.x); a0 += w2 * v.x; a1 += w2 * v.y;
        v = unpack_h2(p2.y); a2 += w2 * v.x; a3 += w2 * v.y;
        v = unpack_h2(p3.x); a0 += w3 * v.x; a1 += w3 * v.y;
        v = unpack_h2(p3.y); a2 += w3 * v.x; a3 += w3 * v.y;
    }
    uint2 o = make_uint2(pack_h2(a0, a1), pack_h2(a2, a3));
    *(uint2*)(g_Ah + (size_t)b * FH + lane * 2) = o;
}

#define MMA_F16(d, a0, a1, a2, a3, b0, b1)                                    \
    asm volatile("mma.sync.aligned.m16n8k16.row.col.f32.f16.f16.f32 "         \
                 "{%0,%1,%2,%3}, {%4,%5,%6,%7}, {%8,%9}, {%0,%1,%2,%3};"      \
                 : "+f"((d)[0]), "+f"((d)[1]), "+f"((d)[2]), "+f"((d)[3])     \
                 : "r"(a0), "r"(a1), "r"(a2), "r"(a3), "r"(b0), "r"(b1))

// ---------------- combine: out = relu?( [A0|A1|A2|A3|Xin] @ [W;root] + b ) ----------------
// fp16 tensor-core GEMM (m16n8k16, fp32 acc), DOUBLE-BUFFERED smem: one sync per tile.
// BM=64, BN=128, BK=32, 256 threads = 8 warps (2x4), warp tile 32x32.
__global__ void __launch_bounds__(256, 2)
k_combine(const float* __restrict__ bias, float* __restrict__ out, int layer) {
    __shared__ uint32_t Xs[2][64][20];    // half2 A tiles: 16 k-pairs + pad 4
    __shared__ uint32_t Wh[2][128][20];   // half2 B tiles [col][k-pair]: 16 + pad 4

    const uint32_t* Xin = (layer == 0) ? g_xh : g_hh;

    int t    = threadIdx.x;
    int lane = t & 31;
    int w    = t >> 5;          // warp 0..7
    int wm   = w & 1;           // row group: rows wm*32..+31
    int wn   = w >> 1;          // col group: cols wn*32..+31
    int gid  = lane >> 2;       // 0..7
    int tid4 = lane & 3;        // 0..3
    int row0 = blockIdx.x * 64;

    float acc[2][4][4];
    #pragma unroll
    for (int mt = 0; mt < 2; mt++)
        #pragma unroll
        for (int nt = 0; nt < 4; nt++)
            #pragma unroll
            for (int q = 0; q < 4; q++) acc[mt][nt][q] = 0.f;

    int arow = t >> 2;          // A: 64 rows x 4 uint4 slots; 1/thread
    int aq   = t & 3;
    int wn_[2], wq[2];          // B: 128 cols x 4 uint4 slots; 2/thread
    #pragma unroll
    for (int it = 0; it < 2; it++) {
        int idx = t + it * 256;
        wn_[it] = idx >> 2;
        wq[it]  = idx & 3;
    }

    uint4 pa, pw[2];
    #define LOAD_TILE(tile)                                                         \
    do {                                                                            \
        int seg_ = (tile) >> 2;                                                     \
        int kc_  = (tile) & 3;                                                      \
        const uint32_t* srcA_ = (seg_ < 4) ? (g_Ah + (size_t)seg_ * N_NODES * FH) : Xin; \
        const uint32_t* wt_ = g_Wth + (((size_t)layer * 5 + seg_) * 4 + kc_) * 2048;\
        int grow_ = row0 + arow;                                                    \
        pa = (grow_ < N_NODES)                                                      \
           ? *(const uint4*)(srcA_ + (size_t)grow_ * FH + kc_ * 16 + aq * 4)        \
           : make_uint4(0u, 0u, 0u, 0u);                                            \
        _Pragma("unroll")                                                           \
        for (int it = 0; it < 2; it++)                                              \
            pw[it] = *(const uint4*)(wt_ + wn_[it] * 16 + wq[it] * 4);              \
    } while (0)

    #define STS_TILE(buf)                                                           \
    do {                                                                            \
        *(uint4*)&Xs[buf][arow][aq * 4] = pa;                                       \
        _Pragma("unroll")                                                           \
        for (int it = 0; it < 2; it++)                                              \
            *(uint4*)&Wh[buf][wn_[it]][wq[it] * 4] = pw[it];                        \
    } while (0)

    LOAD_TILE(0);
    STS_TILE(0);
    __syncthreads();

    for (int tile = 0; tile < NTILES; tile++) {
        int buf = tile & 1;
        if (tile + 1 < NTILES) LOAD_TILE(tile + 1);   // overlap with mma below

        #pragma unroll
        for (int kk = 0; kk < 16; kk += 8) {
            uint32_t a[2][4];
            #pragma unroll
            for (int mt = 0; mt < 2; mt++) {
                int row = wm * 32 + mt * 16 + gid;
                a[mt][0] = Xs[buf][row][kk + tid4];
                a[mt][1] = Xs[buf][row + 8][kk + tid4];
                a[mt][2] = Xs[buf][row][kk + tid4 + 4];
                a[mt][3] = Xs[buf][row + 8][kk + tid4 + 4];
            }
            #pragma unroll
            for (int nt = 0; nt < 4; nt++) {
                int col = wn * 32 + nt * 8 + gid;
                uint32_t b0 = Wh[buf][col][kk + tid4];
                uint32_t b1 = Wh[buf][col][kk + tid4 + 4];
                MMA_F16(acc[0][nt], a[0][0], a[0][1], a[0][2], a[0][3], b0, b1);
                MMA_F16(acc[1][nt], a[1][0], a[1][1], a[1][2], a[1][3], b0, b1);
            }
        }

        if (tile + 1 < NTILES) {
            STS_TILE(buf ^ 1);       // other buffer: no conflict with this tile's reads
            __syncthreads();         // publish before next iter's mma
        }
    }
    #undef LOAD_TILE
    #undef STS_TILE

    #pragma unroll
    for (int mt = 0; mt < 2; mt++) {
        int rbase = row0 + wm * 32 + mt * 16 + gid;
        #pragma unroll
        for (int half = 0; half < 2; half++) {
            int grow = rbase + half * 8;
            if (grow >= N_NODES) continue;
            #pragma unroll
            for (int nt = 0; nt < 4; nt++) {
                int col = wn * 32 + nt * 8 + tid4 * 2;
                float v0 = acc[mt][nt][half * 2 + 0] + __ldg(&bias[col]);
                float v1 = acc[mt][nt][half * 2 + 1] + __ldg(&bias[col + 1]);
                if (layer == 0) {
                    v0 = fmaxf(v0, 0.f); v1 = fmaxf(v1, 0.f);
                    g_hh[(size_t)grow * FH + (col >> 1)] = pack_h2(v0, v1);
                } else {
                    *(float2*)(out + (size_t)grow * F + col) = make_float2(v0, v1);
                }
            }
        }
    }
}

// ---------------- launcher ----------------
// Launch order puts k_combine(layer 0) at slot 6 so ncu (-s 5 -c 1) captures it.
extern "C" void kernel_launch(void* const* d_in, const int* in_sizes, int n_in,
                              void* d_out, int out_size) {
    const float* x     = (const float*)d_in[0];
    const int*   ei    = (const int*)d_in[1];     // [2, E]
    const int*   srcp  = ei;
    const int*   dstp  = ei + N_EDGES;
    const int*   et    = (const int*)d_in[2];
    const float* ew    = (const float*)d_in[3];
    const float* W1    = (const float*)d_in[4];
    const float* root1 = (const float*)d_in[5];
    const float* b1    = (const float*)d_in[6];
    const float* W2    = (const float*)d_in[7];
    const float* root2 = (const float*)d_in[8];
    const float* b2    = (const float*)d_in[9];
    float* out = (float*)d_out;

    const int bblocks = (N_EDGES / 2 + 255) / 256;
    const int cblocks = (N_NODES + 63) / 64;                  // 313
    const int ablocks = (NBUCKETS * 32 + 255) / 256;          // 10000

    // prep (2 launches), minmax, build
    k_prep_a<<<PREPA_TOTAL, 256>>>(x);                        // #1
    k_prep_b<<<PREPB_TOTAL, 256>>>(W1, root1, W2, root2);     // #2
    k_minmax<<<296, 256>>>(ew);                               // #3
    k_build<<<bblocks, 256>>>(srcp, dstp, et, ew);            // #4

    // layer 1
    k_agg<<<ablocks, 256>>>(/*use_h=*/0);                     // #5
    k_combine<<<cblocks, 256>>>(b1, out, /*layer=*/0);        // #6  <- ncu capture slot

    // layer 2
    k_agg<<<ablocks, 256>>>(/*use_h=*/1);                     // #7
    k_combine<<<cblocks, 256>>>(b2, out, /*layer=*/1);        // #8
}

// round 16
// speedup vs baseline: 1.7071x; 1.0597x over previous
#include <cuda_runtime.h>
#include <cuda_fp16.h>
#include <cstdint>

#define N_NODES 20000
#define N_EDGES 320000
#define F 128
#define FH 64             // F/2 half2 per row
#define R 4
#define NBUCKETS (R * N_NODES)
#define CAP 64            // max edges per (relation,dst) bucket; Poisson(4) => P(>=64) ~ 1e-60
#define NTILES 20         // 5 K-segments x 4 k-chunks of 32

// prep_a block ranges (init | x->fp16)
#define PREP_I 313        // zero counters + seed minmax
#define PREP_X 5000       // x -> half2
#define PREPA_TOTAL (PREP_I + PREP_X)
#define PREPB_TOTAL 320   // W pack

// ---------------- scratch (device globals; no allocation allowed) ----------------
__device__ uint32_t g_Ah[(size_t)R * N_NODES * FH];   // per-relation messages, half2 (20.5 MB)
__device__ uint32_t g_xh[(size_t)N_NODES * FH];       // x in half2 (5 MB)
__device__ uint32_t g_hh[(size_t)N_NODES * FH];       // layer-1 output in half2 (5 MB)
__device__ int      g_cnt[NBUCKETS];
__device__ int2     g_slots[(size_t)NBUCKETS * CAP];
__device__ int      g_mn, g_mx;
__device__ uint32_t g_Wth[2 * 5 * 4 * 128 * 16];      // [layer][seg][kc][n][k-pair] half2

__device__ __forceinline__ uint32_t pack_h2(float a, float b) {
    __half2 h = __floats2half2_rn(a, b);
    return *(uint32_t*)&h;
}
__device__ __forceinline__ float2 unpack_h2(uint32_t u) {
    return __half22float2(*(__half2*)&u);
}

// ---------------- prep A: counters+seeds | x->fp16 ----------------
__global__ void k_prep_a(const float* __restrict__ x) {
    int blk = blockIdx.x;
    if (blk < PREP_I) {
        int i = blk * 256 + threadIdx.x;
        if (i == 0) { g_mn = 0x7f800000; g_mx = 0; }
        if (i < NBUCKETS) g_cnt[i] = 0;
    } else {
        int i = (blk - PREP_I) * 256 + threadIdx.x;   // half2 index
        if (i < N_NODES * FH) {
            float2 v = ((const float2*)x)[i];
            g_xh[i] = pack_h2(v.x, v.y);
        }
    }
}

// ---------------- prep B: W transpose + fp16 pack ----------------
__global__ void k_prep_b(const float* __restrict__ W1, const float* __restrict__ r1,
                         const float* __restrict__ W2, const float* __restrict__ r2) {
    int idx = blockIdx.x * 256 + threadIdx.x;         // 2*5*128*64 half2 slots
    if (idx >= 2 * 5 * 128 * 64) return;
    int layer = idx / 40960;
    int rem   = idx % 40960;
    int seg   = rem / 8192;
    int nj    = rem % 8192;        // n*64 + j
    int n     = nj >> 6;
    int j     = nj & 63;           // k-pair 0..63
    const float* src = (layer == 0) ? ((seg < 4) ? W1 + seg * 16384 : r1)
                                    : ((seg < 4) ? W2 + seg * 16384 : r2);
    uint32_t v = pack_h2(src[(2 * j) * 128 + n], src[(2 * j + 1) * 128 + n]);
    g_Wth[((((size_t)layer * 5 + seg) * 4 + (j >> 4)) * 128 + n) * 16 + (j & 15)] = v;
}

// ---------------- minmax: grid-stride + block reduction -> 2 atomics/block ----------------
__global__ void k_minmax(const float* __restrict__ ew) {
    __shared__ float smn[8], smx[8];
    int tid  = threadIdx.x;
    int lane = tid & 31;
    int wid  = tid >> 5;

    float mn = __int_as_float(0x7f800000), mx = 0.f;
    for (int i = blockIdx.x * blockDim.x + tid; i < N_EDGES; i += gridDim.x * blockDim.x) {
        float v = ew[i];
        mn = fminf(mn, v);
        mx = fmaxf(mx, v);
    }
    #pragma unroll
    for (int o = 16; o; o >>= 1) {
        mn = fminf(mn, __shfl_xor_sync(0xffffffffu, mn, o));
        mx = fmaxf(mx, __shfl_xor_sync(0xffffffffu, mx, o));
    }
    if (lane == 0) { smn[wid] = mn; smx[wid] = mx; }
    __syncthreads();
    if (wid == 0) {
        mn = smn[lane & 7]; mx = smx[lane & 7];
        #pragma unroll
        for (int o = 4; o; o >>= 1) {
            mn = fminf(mn, __shfl_xor_sync(0xffffffffu, mn, o));
            mx = fmaxf(mx, __shfl_xor_sync(0xffffffffu, mx, o));
        }
        if (lane == 0) {
            atomicMin(&g_mn, __float_as_int(mn));
            atomicMax(&g_mx, __float_as_int(mx));
        }
    }
}

// ---------------- bucket build; 2 edges/thread ----------------
__global__ void k_build(const int* __restrict__ src, const int* __restrict__ dst,
                        const int* __restrict__ et, const float* __restrict__ ew) {
    int base = (blockIdx.x * blockDim.x + threadIdx.x) * 2;
    float mn = __int_as_float(g_mn);
    float mx = __int_as_float(g_mx);
    float inv = 1.0f / (mx - mn + 1e-8f);
    #pragma unroll
    for (int j = 0; j < 2; j++) {
        int e = base + j;
        if (e >= N_EDGES) break;
        float w = (ew[e] - mn) * inv;
        int b = et[e] * N_NODES + dst[e];
        int slot = atomicAdd(&g_cnt[b], 1);
        if (slot < CAP)
            g_slots[(size_t)b * CAP + slot] = make_int2(src[e], __float_as_int(w));
    }
}

// ---------------- aggregate (R12 version: 1 bucket/warp, uint2 lanes; best measured) ------
__global__ void k_agg(int use_h) {
    int b = (int)(((size_t)blockIdx.x * blockDim.x + threadIdx.x) >> 5);
    if (b >= NBUCKETS) return;
    int lane = threadIdx.x & 31;
    const uint32_t* xin = use_h ? g_hh : g_xh;

    int n = g_cnt[b];
    n = n > CAP ? CAP : n;
    const int2* sl = g_slots + (size_t)b * CAP;

    float a0 = 0.f, a1 = 0.f, a2 = 0.f, a3 = 0.f;
    for (int i = 0; i < n; i += 4) {
        int4 ea = __ldg((const int4*)&sl[i]);
        int4 eb = __ldg((const int4*)&sl[i + 2]);
        float w0 = (i + 0 < n) ? __int_as_float(ea.y) : 0.f;
        float w1 = (i + 1 < n) ? __int_as_float(ea.w) : 0.f;
        float w2 = (i + 2 < n) ? __int_as_float(eb.y) : 0.f;
        float w3 = (i + 3 < n) ? __int_as_float(eb.w) : 0.f;
        unsigned s0 = min((unsigned)ea.x, (unsigned)(N_NODES - 1));
        unsigned s1 = min((unsigned)ea.z, (unsigned)(N_NODES - 1));
        unsigned s2 = min((unsigned)eb.x, (unsigned)(N_NODES - 1));
        unsigned s3 = min((unsigned)eb.z, (unsigned)(N_NODES - 1));
        uint2 p0 = *(const uint2*)(xin + (size_t)s0 * FH + lane * 2);
        uint2 p1 = *(const uint2*)(xin + (size_t)s1 * FH + lane * 2);
        uint2 p2 = *(const uint2*)(xin + (size_t)s2 * FH + lane * 2);
        uint2 p3 = *(const uint2*)(xin + (size_t)s3 * FH + lane * 2);
        float2 v;
        v = unpack_h2(p0.x); a0 += w0 * v.x; a1 += w0 * v.y;
        v = unpack_h2(p0.y); a2 += w0 * v.x; a3 += w0 * v.y;
        v = unpack_h2(p1.x); a0 += w1 * v.x; a1 += w1 * v.y;
        v = unpack_h2(p1.y); a2 += w1 * v.x; a3 += w1 * v.y;
        v = unpack_h2(p2.x); a0 += w2 * v.x; a1 += w2 * v.y;
        v = unpack_h2(p2.y); a2 += w2 * v.x; a3 += w2 * v.y;
        v = unpack_h2(p3.x); a0 += w3 * v.x; a1 += w3 * v.y;
        v = unpack_h2(p3.y); a2 += w3 * v.x; a3 += w3 * v.y;
    }
    uint2 o = make_uint2(pack_h2(a0, a1), pack_h2(a2, a3));
    *(uint2*)(g_Ah + (size_t)b * FH + lane * 2) = o;
}

#define MMA_F16(d, a0, a1, a2, a3, b0, b1)                                    \
    asm volatile("mma.sync.aligned.m16n8k16.row.col.f32.f16.f16.f32 "         \
                 "{%0,%1,%2,%3}, {%4,%5,%6,%7}, {%8,%9}, {%0,%1,%2,%3};"      \
                 : "+f"((d)[0]), "+f"((d)[1]), "+f"((d)[2]), "+f"((d)[3])     \
                 : "r"(a0), "r"(a1), "r"(a2), "r"(a3), "r"(b0), "r"(b1))

#define LDSM_X4(r, addr)                                                      \
    asm volatile("ldmatrix.sync.aligned.m8n8.x4.shared.b16 {%0,%1,%2,%3}, [%4];" \
                 : "=r"((r)[0]), "=r"((r)[1]), "=r"((r)[2]), "=r"((r)[3])     \
                 : "r"(addr))

// ---------------- combine: out = relu?( [A0|A1|A2|A3|Xin] @ [W;root] + b ) ----------------
// fp16 tensor-core GEMM (m16n8k16, fp32 acc), double-buffered smem, ldmatrix fragments:
// 4 LDSM.x4 per k8-step replace 16 LDS.32. BM=64, BN=128, 8 warps (2x4), warp tile 32x32.
__global__ void __launch_bounds__(256, 2)
k_combine(const float* __restrict__ bias, float* __restrict__ out, int layer) {
    __shared__ uint32_t Xs[2][64][20];    // half2 A tiles: 16 k-pairs + pad 4
    __shared__ uint32_t Wh[2][128][20];   // half2 B tiles [col][k-pair]: 16 + pad 4

    const uint32_t* Xin = (layer == 0) ? g_xh : g_hh;

    int t    = threadIdx.x;
    int lane = t & 31;
    int w    = t >> 5;          // warp 0..7
    int wm   = w & 1;           // row group: rows wm*32..+31
    int wn   = w >> 1;          // col group: cols wn*32..+31
    int gid  = lane >> 2;       // 0..7
    int tid4 = lane & 3;        // 0..3
    int row0 = blockIdx.x * 64;

    float acc[2][4][4];
    #pragma unroll
    for (int mt = 0; mt < 2; mt++)
        #pragma unroll
        for (int nt = 0; nt < 4; nt++)
            #pragma unroll
            for (int q = 0; q < 4; q++) acc[mt][nt][q] = 0.f;

    int arow = t >> 2;          // A: 64 rows x 4 uint4 slots; 1/thread
    int aq   = t & 3;
    int wn_[2], wq[2];          // B: 128 cols x 4 uint4 slots; 2/thread
    #pragma unroll
    for (int it = 0; it < 2; it++) {
        int idx = t + it * 256;
        wn_[it] = idx >> 2;
        wq[it]  = idx & 3;
    }

    // ldmatrix byte offsets (computed once).
    // A x4 blocks: [m0,k0][m8,k0][m0,k8][m8,k8] = mma {a0,a1,a2,a3}
    int row_a = (lane & 7) + ((lane >> 3) & 1) * 8;
    int csh_a = (lane >> 4) * 4;                      // uint32 col shift
    uint32_t aoff[2];
    #pragma unroll
    for (int mt = 0; mt < 2; mt++)
        aoff[mt] = (uint32_t)(((wm * 32 + mt * 16 + row_a) * 20 + csh_a) * 4);
    // B x4 blocks: [n(2p),k0][n(2p),k8][n(2p+1),k0][n(2p+1),k8] = {b0,b1,b0',b1'}
    int row_b = (lane & 7) + (lane >> 4) * 8;
    int csh_b = ((lane >> 3) & 1) * 4;
    uint32_t boff[2];
    #pragma unroll
    for (int p = 0; p < 2; p++)
        boff[p] = (uint32_t)(((wn * 32 + p * 16 + row_b) * 20 + csh_b) * 4);

    uint32_t xs_base = (uint32_t)__cvta_generic_to_shared(&Xs[0][0][0]);
    uint32_t wh_base = (uint32_t)__cvta_generic_to_shared(&Wh[0][0][0]);

    uint4 pa, pw[2];
    #define LOAD_TILE(tile)                                                         \
    do {                                                                            \
        int seg_ = (tile) >> 2;                                                     \
        int kc_  = (tile) & 3;                                                      \
        const uint32_t* srcA_ = (seg_ < 4) ? (g_Ah + (size_t)seg_ * N_NODES * FH) : Xin; \
        const uint32_t* wt_ = g_Wth + (((size_t)layer * 5 + seg_) * 4 + kc_) * 2048;\
        int grow_ = row0 + arow;                                                    \
        pa = (grow_ < N_NODES)                                                      \
           ? *(const uint4*)(srcA_ + (size_t)grow_ * FH + kc_ * 16 + aq * 4)        \
           : make_uint4(0u, 0u, 0u, 0u);                                            \
        _Pragma("unroll")                                                           \
        for (int it = 0; it < 2; it++)                                              \
            pw[it] = *(const uint4*)(wt_ + wn_[it] * 16 + wq[it] * 4);              \
    } while (0)

    #define STS_TILE(buf)                                                           \
    do {                                                                            \
        *(uint4*)&Xs[buf][arow][aq * 4] = pa;                                       \
        _Pragma("unroll")                                                           \
        for (int it = 0; it < 2; it++)                                              \
            *(uint4*)&Wh[buf][wn_[it]][wq[it] * 4] = pw[it];                        \
    } while (0)

    LOAD_TILE(0);
    STS_TILE(0);
    __syncthreads();

    for (int tile = 0; tile < NTILES; tile++) {
        int buf = tile & 1;
        uint32_t xsb = xs_base + (uint32_t)buf * (64 * 20 * 4);
        uint32_t whb = wh_base + (uint32_t)buf * (128 * 20 * 4);
        if (tile + 1 < NTILES) LOAD_TILE(tile + 1);   // overlap with mma below

        #pragma unroll
        for (int kk = 0; kk < 16; kk += 8) {
            uint32_t af0[4], af1[4], bf0[4], bf1[4];
            LDSM_X4(af0, xsb + aoff[0] + kk * 4);
            LDSM_X4(af1, xsb + aoff[1] + kk * 4);
            LDSM_X4(bf0, whb + boff[0] + kk * 4);
            LDSM_X4(bf1, whb + boff[1] + kk * 4);
            MMA_F16(acc[0][0], af0[0], af0[1], af0[2], af0[3], bf0[0], bf0[1]);
            MMA_F16(acc[1][0], af1[0], af1[1], af1[2], af1[3], bf0[0], bf0[1]);
            MMA_F16(acc[0][1], af0[0], af0[1], af0[2], af0[3], bf0[2], bf0[3]);
            MMA_F16(acc[1][1], af1[0], af1[1], af1[2], af1[3], bf0[2], bf0[3]);
            MMA_F16(acc[0][2], af0[0], af0[1], af0[2], af0[3], bf1[0], bf1[1]);
            MMA_F16(acc[1][2], af1[0], af1[1], af1[2], af1[3], bf1[0], bf1[1]);
            MMA_F16(acc[0][3], af0[0], af0[1], af0[2], af0[3], bf1[2], bf1[3]);
            MMA_F16(acc[1][3], af1[0], af1[1], af1[2], af1[3], bf1[2], bf1[3]);
        }

        if (tile + 1 < NTILES) {
            STS_TILE(buf ^ 1);       // other buffer: no conflict with this tile's reads
            __syncthreads();         // publish before next iter's mma
        }
    }
    #undef LOAD_TILE
    #undef STS_TILE

    #pragma unroll
    for (int mt = 0; mt < 2; mt++) {
        int rbase = row0 + wm * 32 + mt * 16 + gid;
        #pragma unroll
        for (int half = 0; half < 2; half++) {
            int grow = rbase + half * 8;
            if (grow >= N_NODES) continue;
            #pragma unroll
            for (int nt = 0; nt < 4; nt++) {
                int col = wn * 32 + nt * 8 + tid4 * 2;
                float v0 = acc[mt][nt][half * 2 + 0] + __ldg(&bias[col]);
                float v1 = acc[mt][nt][half * 2 + 1] + __ldg(&bias[col + 1]);
                if (layer == 0) {
                    v0 = fmaxf(v0, 0.f); v1 = fmaxf(v1, 0.f);
                    g_hh[(size_t)grow * FH + (col >> 1)] = pack_h2(v0, v1);
                } else {
                    *(float2*)(out + (size_t)grow * F + col) = make_float2(v0, v1);
                }
            }
        }
    }
}

// ---------------- launcher ----------------
// Launch order puts k_combine(layer 0) at slot 6 so ncu (-s 5 -c 1) captures it.
extern "C" void kernel_launch(void* const* d_in, const int* in_sizes, int n_in,
                              void* d_out, int out_size) {
    const float* x     = (const float*)d_in[0];
    const int*   ei    = (const int*)d_in[1];     // [2, E]
    const int*   srcp  = ei;
    const int*   dstp  = ei + N_EDGES;
    const int*   et    = (const int*)d_in[2];
    const float* ew    = (const float*)d_in[3];
    const float* W1    = (const float*)d_in[4];
    const float* root1 = (const float*)d_in[5];
    const float* b1    = (const float*)d_in[6];
    const float* W2    = (const float*)d_in[7];
    const float* root2 = (const float*)d_in[8];
    const float* b2    = (const float*)d_in[9];
    float* out = (float*)d_out;

    const int bblocks = (N_EDGES / 2 + 255) / 256;
    const int cblocks = (N_NODES + 63) / 64;                  // 313
    const int ablocks = (NBUCKETS * 32 + 255) / 256;          // 10000

    // prep (2 launches), minmax, build
    k_prep_a<<<PREPA_TOTAL, 256>>>(x);                        // #1
    k_prep_b<<<PREPB_TOTAL, 256>>>(W1, root1, W2, root2);     // #2
    k_minmax<<<296, 256>>>(ew);                               // #3
    k_build<<<bblocks, 256>>>(srcp, dstp, et, ew);            // #4

    // layer 1
    k_agg<<<ablocks, 256>>>(/*use_h=*/0);                     // #5
    k_combine<<<cblocks, 256>>>(b1, out, /*layer=*/0);        // #6  <- ncu capture slot

    // layer 2
    k_agg<<<ablocks, 256>>>(/*use_h=*/1);                     // #7
    k_combine<<<cblocks, 256>>>(b2, out, /*layer=*/1);        // #8
}